// round 13
// baseline (speedup 1.0000x reference)
#include <cuda_runtime.h>
#include <cuda_fp16.h>
#include <cstdint>

// Problem constants
#define B_  4
#define N_  4096
#define D_  1024
#define U_  1024

// Scratch (device globals; no runtime allocation)
__device__ __half g_Xh  [(size_t)B_ * N_ * D_];      // X as half
__device__ __half g_QKVh[(size_t)B_ * N_ * 3 * U_];  // [M, 3072]: Q | K | V columns
__device__ __half g_P   [(size_t)B_ * N_ * N_];      // unnormalized probs exp(s)
__device__ float  g_RS  [64 * (size_t)B_ * N_];      // per-slot row partial sums
__device__ float  g_INV [(size_t)B_ * N_];           // 1 / rowsum
__device__ __half g_WTh [3 * (size_t)D_ * U_];       // WQ^T | WK^T | WV^T stacked

// ---------------------------------------------------------------------------
#define MMA_F16(c, a, b)                                                       \
    asm volatile("mma.sync.aligned.m16n8k16.row.col.f32.f16.f16.f32 "         \
        "{%0,%1,%2,%3}, {%4,%5,%6,%7}, {%8,%9}, {%0,%1,%2,%3};"               \
        : "+f"((c)[0]), "+f"((c)[1]), "+f"((c)[2]), "+f"((c)[3])              \
        : "r"((a)[0]), "r"((a)[1]), "r"((a)[2]), "r"((a)[3]),                 \
          "r"((b)[0]), "r"((b)[1]))

#define LDSM_X4(r0, r1, r2, r3, addr)                                          \
    asm volatile("ldmatrix.sync.aligned.m8n8.x4.shared.b16 {%0,%1,%2,%3}, [%4];" \
        : "=r"(r0), "=r"(r1), "=r"(r2), "=r"(r3) : "r"(addr))

#define LDSM_X4_T(r0, r1, r2, r3, addr)                                        \
    asm volatile("ldmatrix.sync.aligned.m8n8.x4.trans.shared.b16 {%0,%1,%2,%3}, [%4];" \
        : "=r"(r0), "=r"(r1), "=r"(r2), "=r"(r3) : "r"(addr))

// ---------------------------------------------------------------------------
// fp16 mma.sync GEMM, fp32 accum. BM=BN=128, BK=64, 256 threads (8 warps,
// each 32x64), 3-stage cp.async, 2 CTAs/SM, one barrier per k-tile.
//  TB_NN=false: NT   C = A[M,K] @ B[N,K]^T   (B row-major [N,K])
//  TB_NN=true : NN   C = A[M,K] @ B[K,N]     (B row-major [K,N], trans-ldsm)
// MODE 1: C half = acc*alpha                      (projections)
// MODE 2: C half = exp(acc*alpha); row partials -> aux[64][B*N]  (scores)
// MODE 3: C fp32 = acc * aux[row]                 (PV, 1/rowsum scaling)
// ---------------------------------------------------------------------------
template <int MODE, bool TB_NN>
__global__ __launch_bounds__(256, 2)
void gemm_f16(const __half* __restrict__ A, const __half* __restrict__ B,
              void* __restrict__ Cv, int K, int lda, int ldb, int ldc,
              long long sA, long long sB, long long sC, float alpha,
              float* __restrict__ aux)
{
    constexpr int BM = 128, BN = 128, BK = 64, S = 3;
    constexpr int LDSH = 72;                       // A tile row stride (halves)
    constexpr int LDSB = TB_NN ? 136 : 72;         // B tile row stride (halves)
    constexpr int ATILE = BM * LDSH;               // 9216 halves
    constexpr int BTILE = TB_NN ? (BK * 136) : (BN * 72);   // 8704 / 9216
    constexpr int STAGE = ATILE + BTILE;
    extern __shared__ __half smh[];

    const int tid  = threadIdx.x;
    const int wid  = tid >> 5, lane = tid & 31;
    const int g    = lane >> 2, t = lane & 3;
    const int wm   = wid >> 1, wn = wid & 1;

    const long long rowBase = (long long)blockIdx.y * BM;
    const long long colBase = (long long)blockIdx.x * BN;
    A += (long long)blockIdx.z * sA + rowBase * lda;
    B += (long long)blockIdx.z * sB + (TB_NN ? colBase : colBase * ldb);

    const uint32_t smem0 = (uint32_t)__cvta_generic_to_shared(smh);

    // A fragment ldmatrix offset (halves): row = lane&15 (+16*mt), col = 8*(lane>>4)
    const uint32_t aoff = (uint32_t)((32 * wm + (lane & 15)) * LDSH + 8 * (lane >> 4));
    // B fragment offset:
    //  NT  (smem [n][k]): row_n = 8*(lane>>4) + (lane&7), col_k = 8*((lane>>3)&1)
    //  NN  (smem [k][n], trans): row_k = (lane&7) + 8*((lane>>3)&1), col_n = 8*(lane>>4)
    const uint32_t boff = TB_NN
        ? (uint32_t)(((lane & 7) + 8 * ((lane >> 3) & 1)) * LDSB + 64 * wn + 8 * (lane >> 4))
        : (uint32_t)((64 * wn + ((lane >> 4) << 3) + (lane & 7)) * LDSB + 8 * ((lane >> 3) & 1));

    const int r0 = tid >> 3, c0 = tid & 7;         // NT loader coords
    const int rb = tid >> 4, cb = tid & 15;        // NN B loader coords

    auto load_tile = [&](int kt) {
        uint32_t as = smem0 + (uint32_t)((kt % S) * STAGE) * 2;
        uint32_t bs = as + ATILE * 2;
        const __half* ag = A + (long long)kt * BK;
        #pragma unroll
        for (int i = 0; i < 4; i++) {
            int r = r0 + 32 * i;
            uint32_t d = as + (uint32_t)(r * LDSH + c0 * 8) * 2;
            asm volatile("cp.async.cg.shared.global [%0], [%1], 16;"
                         :: "r"(d), "l"(ag + (long long)r * lda + c0 * 8));
        }
        if (TB_NN) {
            // B tile: rows k = kt*64 .. +64, cols colBase .. +128
            const __half* bg = B + (long long)kt * BK * ldb;
            #pragma unroll
            for (int i = 0; i < 4; i++) {
                int r = rb + 16 * i;               // k row 0..63
                uint32_t d = bs + (uint32_t)(r * LDSB + cb * 8) * 2;
                asm volatile("cp.async.cg.shared.global [%0], [%1], 16;"
                             :: "r"(d), "l"(bg + (long long)r * ldb + cb * 8));
            }
        } else {
            const __half* bg = B + (long long)kt * BK;
            #pragma unroll
            for (int i = 0; i < 4; i++) {
                int r = r0 + 32 * i;               // n row 0..127
                uint32_t d = bs + (uint32_t)(r * LDSB + c0 * 8) * 2;
                asm volatile("cp.async.cg.shared.global [%0], [%1], 16;"
                             :: "r"(d), "l"(bg + (long long)r * ldb + c0 * 8));
            }
        }
        asm volatile("cp.async.commit_group;");
    };

    const int NT = K / BK;
    load_tile(0);
    load_tile(1);

    float acc[2][8][4];
    #pragma unroll
    for (int mt = 0; mt < 2; mt++)
        #pragma unroll
        for (int nt = 0; nt < 8; nt++)
            #pragma unroll
            for (int j = 0; j < 4; j++) acc[mt][nt][j] = 0.f;

    for (int kt = 0; kt < NT; kt++) {
        if (kt < NT - 1) asm volatile("cp.async.wait_group 1;");
        else             asm volatile("cp.async.wait_group 0;");
        __syncthreads();

        const uint32_t as = smem0 + (uint32_t)((kt % S) * STAGE) * 2;
        const uint32_t bs = as + ATILE * 2;
        const uint32_t aaddr = as + aoff * 2;
        const uint32_t baddr = bs + boff * 2;

        // per-ks strides: A k-advance 16 halves in-row; B: NT 16 halves in-row,
        // NN 16 rows (=16*LDSB). per-p (n-pair): NT 16 rows, NN 16 halves in-row.
        uint32_t a[2][4], b[8][2];
        #pragma unroll
        for (int mt = 0; mt < 2; mt++)
            LDSM_X4(a[mt][0], a[mt][1], a[mt][2], a[mt][3],
                    aaddr + (uint32_t)(16 * mt * LDSH) * 2);
        #pragma unroll
        for (int p = 0; p < 4; p++) {
            uint32_t ba = baddr + (TB_NN ? (uint32_t)(16 * p) * 2
                                         : (uint32_t)(16 * p * LDSB) * 2);
            if (TB_NN) LDSM_X4_T(b[2*p][0], b[2*p][1], b[2*p+1][0], b[2*p+1][1], ba);
            else       LDSM_X4  (b[2*p][0], b[2*p][1], b[2*p+1][0], b[2*p+1][1], ba);
        }

        if (kt + S - 1 < NT) load_tile(kt + S - 1);

        #pragma unroll
        for (int mt = 0; mt < 2; mt++)
            #pragma unroll
            for (int nt = 0; nt < 8; nt++)
                MMA_F16(acc[mt][nt], a[mt], b[nt]);

        #pragma unroll
        for (int ks = 1; ks < 4; ks++) {
            const uint32_t kbA = (uint32_t)(16 * ks) * 2;
            const uint32_t kbB = TB_NN ? (uint32_t)(16 * ks * LDSB) * 2
                                       : (uint32_t)(16 * ks) * 2;
            #pragma unroll
            for (int mt = 0; mt < 2; mt++)
                LDSM_X4(a[mt][0], a[mt][1], a[mt][2], a[mt][3],
                        aaddr + (uint32_t)(16 * mt * LDSH) * 2 + kbA);
            #pragma unroll
            for (int p = 0; p < 4; p++) {
                uint32_t ba = baddr + kbB + (TB_NN ? (uint32_t)(16 * p) * 2
                                                   : (uint32_t)(16 * p * LDSB) * 2);
                if (TB_NN) LDSM_X4_T(b[2*p][0], b[2*p][1], b[2*p+1][0], b[2*p+1][1], ba);
                else       LDSM_X4  (b[2*p][0], b[2*p][1], b[2*p+1][0], b[2*p+1][1], ba);
            }
            #pragma unroll
            for (int mt = 0; mt < 2; mt++)
                #pragma unroll
                for (int nt = 0; nt < 8; nt++)
                    MMA_F16(acc[mt][nt], a[mt], b[nt]);
        }
    }

    // ---------------- epilogues ----------------
    if (MODE == 1) {
        __half* C = (__half*)Cv + (long long)blockIdx.z * sC;
        #pragma unroll
        for (int mt = 0; mt < 2; mt++) {
            const long long rlo = rowBase + 32 * wm + 16 * mt + g;
            #pragma unroll
            for (int nt = 0; nt < 8; nt++) {
                const long long col = colBase + 64 * wn + 8 * nt + 2 * t;
                *(__half2*)&C[rlo * ldc + col] =
                    __floats2half2_rn(acc[mt][nt][0] * alpha, acc[mt][nt][1] * alpha);
                *(__half2*)&C[(rlo + 8) * ldc + col] =
                    __floats2half2_rn(acc[mt][nt][2] * alpha, acc[mt][nt][3] * alpha);
            }
        }
    } else if (MODE == 2) {
        __half* C = (__half*)Cv + (long long)blockIdx.z * sC;
        float part[2][2] = {{0.f, 0.f}, {0.f, 0.f}};
        #pragma unroll
        for (int mt = 0; mt < 2; mt++) {
            const long long rlo = rowBase + 32 * wm + 16 * mt + g;
            #pragma unroll
            for (int nt = 0; nt < 8; nt++) {
                const long long col = colBase + 64 * wn + 8 * nt + 2 * t;
                float e0 = __expf(acc[mt][nt][0] * alpha);
                float e1 = __expf(acc[mt][nt][1] * alpha);
                float e2 = __expf(acc[mt][nt][2] * alpha);
                float e3 = __expf(acc[mt][nt][3] * alpha);
                *(__half2*)&C[rlo * ldc + col]       = __floats2half2_rn(e0, e1);
                *(__half2*)&C[(rlo + 8) * ldc + col] = __floats2half2_rn(e2, e3);
                part[mt][0] += e0 + e1;
                part[mt][1] += e2 + e3;
            }
        }
        #pragma unroll
        for (int mt = 0; mt < 2; mt++)
            #pragma unroll
            for (int j = 0; j < 2; j++) {
                float v = part[mt][j];
                v += __shfl_xor_sync(0xFFFFFFFFu, v, 1);
                v += __shfl_xor_sync(0xFFFFFFFFu, v, 2);
                part[mt][j] = v;
            }
        if (t == 0) {
            const long long slot = (long long)(blockIdx.x * 2 + wn);
            #pragma unroll
            for (int mt = 0; mt < 2; mt++) {
                const long long grow = (long long)blockIdx.z * N_ +
                                       rowBase + 32 * wm + 16 * mt + g;
                aux[slot * (B_ * (long long)N_) + grow]     = part[mt][0];
                aux[slot * (B_ * (long long)N_) + grow + 8] = part[mt][1];
            }
        }
    } else {  // MODE == 3
        float* C = (float*)Cv + (long long)blockIdx.z * sC;
        #pragma unroll
        for (int mt = 0; mt < 2; mt++) {
            const long long rlo = rowBase + 32 * wm + 16 * mt + g;
            const float inv0 = aux[(long long)blockIdx.z * N_ + rlo];
            const float inv1 = aux[(long long)blockIdx.z * N_ + rlo + 8];
            #pragma unroll
            for (int nt = 0; nt < 8; nt++) {
                const long long col = colBase + 64 * wn + 8 * nt + 2 * t;
                *(float2*)&C[rlo * ldc + col] =
                    make_float2(acc[mt][nt][0] * inv0, acc[mt][nt][1] * inv0);
                *(float2*)&C[(rlo + 8) * ldc + col] =
                    make_float2(acc[mt][nt][2] * inv1, acc[mt][nt][3] * inv1);
            }
        }
    }
}

// ---------------------------------------------------------------------------
__global__ __launch_bounds__(256)
void to_half_kernel(const float4* __restrict__ in, __half2* __restrict__ out, int n4)
{
    int i = blockIdx.x * blockDim.x + threadIdx.x;
    if (i < n4) {
        float4 v = in[i];
        out[2 * i]     = __floats2half2_rn(v.x, v.y);
        out[2 * i + 1] = __floats2half2_rn(v.z, v.w);
    }
}

// ---------------------------------------------------------------------------
__global__ __launch_bounds__(256)
void transpose3_half_kernel(const float* __restrict__ w0,
                            const float* __restrict__ w1,
                            const float* __restrict__ w2,
                            __half* __restrict__ out)
{
    const float* in = (blockIdx.z == 0) ? w0 : (blockIdx.z == 1) ? w1 : w2;
    __half* o = out + (size_t)blockIdx.z * D_ * U_;

    __shared__ float tbuf[32][33];
    const int tx = threadIdx.x, ty = threadIdx.y;
    const int x = blockIdx.x * 32 + tx;
    const int yb = blockIdx.y * 32;
    #pragma unroll
    for (int i = 0; i < 32; i += 8)
        tbuf[ty + i][tx] = in[(long long)(yb + ty + i) * U_ + x];
    __syncthreads();
    const int xo = yb + tx;
    const int yo = blockIdx.x * 32 + ty;
    #pragma unroll
    for (int i = 0; i < 32; i += 8)
        o[(long long)(yo + i) * D_ + xo] = __float2half_rn(tbuf[tx][ty + i]);
}

// ---------------------------------------------------------------------------
__global__ __launch_bounds__(256)
void rowinv_kernel(const float* __restrict__ buf, float* __restrict__ inv)
{
    const int r = blockIdx.x * blockDim.x + threadIdx.x;   // < B_*N_
    float s = 0.f;
    #pragma unroll
    for (int j = 0; j < 64; j++)
        s += buf[(long long)j * (B_ * (long long)N_) + r];
    inv[r] = 1.f / s;
}

// ---------------------------------------------------------------------------
extern "C" void kernel_launch(void* const* d_in, const int* in_sizes, int n_in,
                              void* d_out, int out_size)
{
    const float* X  = (const float*)d_in[0];
    const float* WQ = (const float*)d_in[1];
    const float* WK = (const float*)d_in[2];
    const float* WV = (const float*)d_in[3];
    float* out = (float*)d_out;

    __half *Xh, *QKVh, *P, *WTh;
    float *RS, *INV;
    cudaGetSymbolAddress((void**)&Xh,   g_Xh);
    cudaGetSymbolAddress((void**)&QKVh, g_QKVh);
    cudaGetSymbolAddress((void**)&P,    g_P);
    cudaGetSymbolAddress((void**)&RS,   g_RS);
    cudaGetSymbolAddress((void**)&INV,  g_INV);
    cudaGetSymbolAddress((void**)&WTh,  g_WTh);
    __half* Qh = QKVh;                            // [M, 3072], ld = 3072
    __half* Kh = QKVh + U_;
    __half* Vh = QKVh + 2 * U_;

    const int SMEM_NT = 3 * (9216 + 9216) * 2;    // 110592 B
    const int SMEM_NN = 3 * (9216 + 8704) * 2;    // 107520 B
    cudaFuncSetAttribute(gemm_f16<1, false>, cudaFuncAttributeMaxDynamicSharedMemorySize, SMEM_NT);
    cudaFuncSetAttribute(gemm_f16<2, false>, cudaFuncAttributeMaxDynamicSharedMemorySize, SMEM_NT);
    cudaFuncSetAttribute(gemm_f16<3, true >, cudaFuncAttributeMaxDynamicSharedMemorySize, SMEM_NN);

    const int M = B_ * N_;                        // 16384
    const long long strQKV = (long long)N_ * 3 * U_;
    const long long strQ   = (long long)N_ * U_;
    const long long strS   = (long long)N_ * N_;

    // 1) X -> half; batched weight transpose -> half ([3072, 1024] stacked)
    to_half_kernel<<<(M * D_ / 4 + 255) / 256, 256>>>((const float4*)X, (__half2*)Xh, M * D_ / 4);
    dim3 tb(32, 8), tg(U_ / 32, D_ / 32, 3);
    transpose3_half_kernel<<<tg, tb>>>(WQ, WK, WV, WTh);

    // 2) fused QKV projection: QKV = Xh @ [WQ^T;WK^T;WV^T]^T -> [16384, 3072]
    dim3 gP(3 * U_ / 128, M / 128, 1);
    gemm_f16<1, false><<<gP, 256, SMEM_NT>>>(Xh, WTh, QKVh, D_, D_, D_, 3 * U_,
                                             0, 0, 0, 1.0f, nullptr);

    // 3) scores + exp fused: P_b = exp((1/32) Q_b K_b^T), row partials -> RS
    dim3 gS(N_ / 128, N_ / 128, B_);
    gemm_f16<2, false><<<gS, 256, SMEM_NT>>>(Qh, Kh, P, U_, 3 * U_, 3 * U_, N_,
                                             strQKV, strQKV, strS, 1.0f / 32.0f, RS);

    // 4) deterministic row-sum -> inverse
    rowinv_kernel<<<M / 256, 256>>>(RS, INV);

    // 5) out_b = (P_b @ V_b) * inv[row]   (NN: V in natural [token, u] layout)
    dim3 gO(U_ / 128, N_ / 128, B_);
    gemm_f16<3, true><<<gO, 256, SMEM_NN>>>(P, Vh, out, N_, N_, 3 * U_, U_,
                                            strS, strQKV, strQ, 1.0f, INV);
}

// round 14
// speedup vs baseline: 1.0782x; 1.0782x over previous
#include <cuda_runtime.h>
#include <cuda_fp16.h>
#include <cstdint>

// Problem constants
#define B_  4
#define N_  4096
#define D_  1024
#define U_  1024

// Scratch (device globals; no runtime allocation)
__device__ __half g_Xh [(size_t)B_ * N_ * D_];   // X as half            (134 MB)
__device__ __half g_T1h[(size_t)B_ * N_ * D_];   // T1 = X @ G           (34 MB)
__device__ __half g_Vh [(size_t)B_ * N_ * U_];   // V  = X @ Wv          (34 MB)
__device__ __half g_Gh [(size_t)D_ * D_];        // G  = Wq @ Wk^T       (2 MB)
__device__ __half g_Wh [3 * (size_t)D_ * U_];    // Wq, Wk, Wv as half   (6 MB)
__device__ __half g_P  [(size_t)B_ * N_ * N_];   // unnormalized exp(s)  (134 MB)
__device__ float  g_RS [64 * (size_t)B_ * N_];   // per-slot row partial sums
__device__ float  g_INV[(size_t)B_ * N_];        // 1 / rowsum

// ---------------------------------------------------------------------------
#define MMA_F16(c, a, b)                                                       \
    asm volatile("mma.sync.aligned.m16n8k16.row.col.f32.f16.f16.f32 "         \
        "{%0,%1,%2,%3}, {%4,%5,%6,%7}, {%8,%9}, {%0,%1,%2,%3};"               \
        : "+f"((c)[0]), "+f"((c)[1]), "+f"((c)[2]), "+f"((c)[3])              \
        : "r"((a)[0]), "r"((a)[1]), "r"((a)[2]), "r"((a)[3]),                 \
          "r"((b)[0]), "r"((b)[1]))

#define LDSM_X4(r0, r1, r2, r3, addr)                                          \
    asm volatile("ldmatrix.sync.aligned.m8n8.x4.shared.b16 {%0,%1,%2,%3}, [%4];" \
        : "=r"(r0), "=r"(r1), "=r"(r2), "=r"(r3) : "r"(addr))

#define LDSM_X4_T(r0, r1, r2, r3, addr)                                        \
    asm volatile("ldmatrix.sync.aligned.m8n8.x4.trans.shared.b16 {%0,%1,%2,%3}, [%4];" \
        : "=r"(r0), "=r"(r1), "=r"(r2), "=r"(r3) : "r"(addr))

// ---------------------------------------------------------------------------
// fp16 mma.sync GEMM, fp32 accum. BM=BN=128, BK=64, 256 threads (8 warps,
// each 32x64), 3-stage cp.async, 2 CTAs/SM, one barrier per k-tile.
//  TB_NN=false: NT   C = A[M,K] @ B[N,K]^T   (B row-major [N,K])
//  TB_NN=true : NN   C = A[M,K] @ B[K,N]     (B row-major [K,N], trans-ldsm)
// MODE 1: C half = acc*alpha
// MODE 2: C half = exp(acc*alpha); row partials -> aux[64][B*N]  (scores)
// MODE 3: C fp32 = acc * aux[row]                                (PV)
// ---------------------------------------------------------------------------
template <int MODE, bool TB_NN>
__global__ __launch_bounds__(256, 2)
void gemm_f16(const __half* __restrict__ A, const __half* __restrict__ B,
              void* __restrict__ Cv, int K, int lda, int ldb, int ldc,
              long long sA, long long sB, long long sC, float alpha,
              float* __restrict__ aux)
{
    constexpr int BM = 128, BN = 128, BK = 64, S = 3;
    constexpr int LDSH = 72;                       // A tile row stride (halves)
    constexpr int LDSB = TB_NN ? 136 : 72;         // B tile row stride (halves)
    constexpr int ATILE = BM * LDSH;
    constexpr int BTILE = TB_NN ? (BK * 136) : (BN * 72);
    constexpr int STAGE = ATILE + BTILE;
    extern __shared__ __half smh[];

    const int tid  = threadIdx.x;
    const int wid  = tid >> 5, lane = tid & 31;
    const int g    = lane >> 2, t = lane & 3;
    const int wm   = wid >> 1, wn = wid & 1;

    const long long rowBase = (long long)blockIdx.y * BM;
    const long long colBase = (long long)blockIdx.x * BN;
    A += (long long)blockIdx.z * sA + rowBase * lda;
    B += (long long)blockIdx.z * sB + (TB_NN ? colBase : colBase * ldb);

    const uint32_t smem0 = (uint32_t)__cvta_generic_to_shared(smh);

    const uint32_t aoff = (uint32_t)((32 * wm + (lane & 15)) * LDSH + 8 * (lane >> 4));
    const uint32_t boff = TB_NN
        ? (uint32_t)(((lane & 7) + 8 * ((lane >> 3) & 1)) * LDSB + 64 * wn + 8 * (lane >> 4))
        : (uint32_t)((64 * wn + ((lane >> 4) << 3) + (lane & 7)) * LDSB + 8 * ((lane >> 3) & 1));

    const int r0 = tid >> 3, c0 = tid & 7;         // NT loader coords
    const int rb = tid >> 4, cb = tid & 15;        // NN B loader coords

    auto load_tile = [&](int kt) {
        uint32_t as = smem0 + (uint32_t)((kt % S) * STAGE) * 2;
        uint32_t bs = as + ATILE * 2;
        const __half* ag = A + (long long)kt * BK;
        #pragma unroll
        for (int i = 0; i < 4; i++) {
            int r = r0 + 32 * i;
            uint32_t d = as + (uint32_t)(r * LDSH + c0 * 8) * 2;
            asm volatile("cp.async.cg.shared.global [%0], [%1], 16;"
                         :: "r"(d), "l"(ag + (long long)r * lda + c0 * 8));
        }
        if (TB_NN) {
            const __half* bg = B + (long long)kt * BK * ldb;
            #pragma unroll
            for (int i = 0; i < 4; i++) {
                int r = rb + 16 * i;
                uint32_t d = bs + (uint32_t)(r * LDSB + cb * 8) * 2;
                asm volatile("cp.async.cg.shared.global [%0], [%1], 16;"
                             :: "r"(d), "l"(bg + (long long)r * ldb + cb * 8));
            }
        } else {
            const __half* bg = B + (long long)kt * BK;
            #pragma unroll
            for (int i = 0; i < 4; i++) {
                int r = r0 + 32 * i;
                uint32_t d = bs + (uint32_t)(r * LDSB + c0 * 8) * 2;
                asm volatile("cp.async.cg.shared.global [%0], [%1], 16;"
                             :: "r"(d), "l"(bg + (long long)r * ldb + c0 * 8));
            }
        }
        asm volatile("cp.async.commit_group;");
    };

    const int NT = K / BK;
    load_tile(0);
    load_tile(1);

    float acc[2][8][4];
    #pragma unroll
    for (int mt = 0; mt < 2; mt++)
        #pragma unroll
        for (int nt = 0; nt < 8; nt++)
            #pragma unroll
            for (int j = 0; j < 4; j++) acc[mt][nt][j] = 0.f;

    for (int kt = 0; kt < NT; kt++) {
        if (kt < NT - 1) asm volatile("cp.async.wait_group 1;");
        else             asm volatile("cp.async.wait_group 0;");
        __syncthreads();

        const uint32_t as = smem0 + (uint32_t)((kt % S) * STAGE) * 2;
        const uint32_t bs = as + ATILE * 2;
        const uint32_t aaddr = as + aoff * 2;
        const uint32_t baddr = bs + boff * 2;

        uint32_t a[2][4], b[8][2];
        #pragma unroll
        for (int mt = 0; mt < 2; mt++)
            LDSM_X4(a[mt][0], a[mt][1], a[mt][2], a[mt][3],
                    aaddr + (uint32_t)(16 * mt * LDSH) * 2);
        #pragma unroll
        for (int p = 0; p < 4; p++) {
            uint32_t ba = baddr + (TB_NN ? (uint32_t)(16 * p) * 2
                                         : (uint32_t)(16 * p * LDSB) * 2);
            if (TB_NN) LDSM_X4_T(b[2*p][0], b[2*p][1], b[2*p+1][0], b[2*p+1][1], ba);
            else       LDSM_X4  (b[2*p][0], b[2*p][1], b[2*p+1][0], b[2*p+1][1], ba);
        }

        if (kt + S - 1 < NT) load_tile(kt + S - 1);

        #pragma unroll
        for (int mt = 0; mt < 2; mt++)
            #pragma unroll
            for (int nt = 0; nt < 8; nt++)
                MMA_F16(acc[mt][nt], a[mt], b[nt]);

        #pragma unroll
        for (int ks = 1; ks < 4; ks++) {
            const uint32_t kbA = (uint32_t)(16 * ks) * 2;
            const uint32_t kbB = TB_NN ? (uint32_t)(16 * ks * LDSB) * 2
                                       : (uint32_t)(16 * ks) * 2;
            #pragma unroll
            for (int mt = 0; mt < 2; mt++)
                LDSM_X4(a[mt][0], a[mt][1], a[mt][2], a[mt][3],
                        aaddr + (uint32_t)(16 * mt * LDSH) * 2 + kbA);
            #pragma unroll
            for (int p = 0; p < 4; p++) {
                uint32_t ba = baddr + kbB + (TB_NN ? (uint32_t)(16 * p) * 2
                                                   : (uint32_t)(16 * p * LDSB) * 2);
                if (TB_NN) LDSM_X4_T(b[2*p][0], b[2*p][1], b[2*p+1][0], b[2*p+1][1], ba);
                else       LDSM_X4  (b[2*p][0], b[2*p][1], b[2*p+1][0], b[2*p+1][1], ba);
            }
            #pragma unroll
            for (int mt = 0; mt < 2; mt++)
                #pragma unroll
                for (int nt = 0; nt < 8; nt++)
                    MMA_F16(acc[mt][nt], a[mt], b[nt]);
        }
    }

    // ---------------- epilogues ----------------
    if (MODE == 1) {
        __half* C = (__half*)Cv + (long long)blockIdx.z * sC;
        #pragma unroll
        for (int mt = 0; mt < 2; mt++) {
            const long long rlo = rowBase + 32 * wm + 16 * mt + g;
            #pragma unroll
            for (int nt = 0; nt < 8; nt++) {
                const long long col = colBase + 64 * wn + 8 * nt + 2 * t;
                *(__half2*)&C[rlo * ldc + col] =
                    __floats2half2_rn(acc[mt][nt][0] * alpha, acc[mt][nt][1] * alpha);
                *(__half2*)&C[(rlo + 8) * ldc + col] =
                    __floats2half2_rn(acc[mt][nt][2] * alpha, acc[mt][nt][3] * alpha);
            }
        }
    } else if (MODE == 2) {
        __half* C = (__half*)Cv + (long long)blockIdx.z * sC;
        float part[2][2] = {{0.f, 0.f}, {0.f, 0.f}};
        #pragma unroll
        for (int mt = 0; mt < 2; mt++) {
            const long long rlo = rowBase + 32 * wm + 16 * mt + g;
            #pragma unroll
            for (int nt = 0; nt < 8; nt++) {
                const long long col = colBase + 64 * wn + 8 * nt + 2 * t;
                float e0 = __expf(acc[mt][nt][0] * alpha);
                float e1 = __expf(acc[mt][nt][1] * alpha);
                float e2 = __expf(acc[mt][nt][2] * alpha);
                float e3 = __expf(acc[mt][nt][3] * alpha);
                *(__half2*)&C[rlo * ldc + col]       = __floats2half2_rn(e0, e1);
                *(__half2*)&C[(rlo + 8) * ldc + col] = __floats2half2_rn(e2, e3);
                part[mt][0] += e0 + e1;
                part[mt][1] += e2 + e3;
            }
        }
        #pragma unroll
        for (int mt = 0; mt < 2; mt++)
            #pragma unroll
            for (int j = 0; j < 2; j++) {
                float v = part[mt][j];
                v += __shfl_xor_sync(0xFFFFFFFFu, v, 1);
                v += __shfl_xor_sync(0xFFFFFFFFu, v, 2);
                part[mt][j] = v;
            }
        if (t == 0) {
            const long long slot = (long long)(blockIdx.x * 2 + wn);
            #pragma unroll
            for (int mt = 0; mt < 2; mt++) {
                const long long grow = (long long)blockIdx.z * N_ +
                                       rowBase + 32 * wm + 16 * mt + g;
                aux[slot * (B_ * (long long)N_) + grow]     = part[mt][0];
                aux[slot * (B_ * (long long)N_) + grow + 8] = part[mt][1];
            }
        }
    } else {  // MODE == 3
        float* C = (float*)Cv + (long long)blockIdx.z * sC;
        #pragma unroll
        for (int mt = 0; mt < 2; mt++) {
            const long long rlo = rowBase + 32 * wm + 16 * mt + g;
            const float inv0 = aux[(long long)blockIdx.z * N_ + rlo];
            const float inv1 = aux[(long long)blockIdx.z * N_ + rlo + 8];
            #pragma unroll
            for (int nt = 0; nt < 8; nt++) {
                const long long col = colBase + 64 * wn + 8 * nt + 2 * t;
                *(float2*)&C[rlo * ldc + col] =
                    make_float2(acc[mt][nt][0] * inv0, acc[mt][nt][1] * inv0);
                *(float2*)&C[(rlo + 8) * ldc + col] =
                    make_float2(acc[mt][nt][2] * inv1, acc[mt][nt][3] * inv1);
            }
        }
    }
}

// ---------------------------------------------------------------------------
__global__ __launch_bounds__(256)
void to_half_kernel(const float4* __restrict__ in, __half2* __restrict__ out, int n4)
{
    int i = blockIdx.x * blockDim.x + threadIdx.x;
    if (i < n4) {
        float4 v = in[i];
        out[2 * i]     = __floats2half2_rn(v.x, v.y);
        out[2 * i + 1] = __floats2half2_rn(v.z, v.w);
    }
}

// 3 weight matrices -> half, one launch (no transposes needed in this dataflow)
__global__ __launch_bounds__(256)
void to_half3_kernel(const float4* __restrict__ w0, const float4* __restrict__ w1,
                     const float4* __restrict__ w2, __half2* __restrict__ out, int n4)
{
    const float4* in = (blockIdx.y == 0) ? w0 : (blockIdx.y == 1) ? w1 : w2;
    __half2* o = out + (size_t)blockIdx.y * n4 * 2;
    int i = blockIdx.x * blockDim.x + threadIdx.x;
    if (i < n4) {
        float4 v = in[i];
        o[2 * i]     = __floats2half2_rn(v.x, v.y);
        o[2 * i + 1] = __floats2half2_rn(v.z, v.w);
    }
}

// ---------------------------------------------------------------------------
__global__ __launch_bounds__(256)
void rowinv_kernel(const float* __restrict__ buf, float* __restrict__ inv)
{
    const int r = blockIdx.x * blockDim.x + threadIdx.x;   // < B_*N_
    float s = 0.f;
    #pragma unroll
    for (int j = 0; j < 64; j++)
        s += buf[(long long)j * (B_ * (long long)N_) + r];
    inv[r] = 1.f / s;
}

// ---------------------------------------------------------------------------
extern "C" void kernel_launch(void* const* d_in, const int* in_sizes, int n_in,
                              void* d_out, int out_size)
{
    const float* X  = (const float*)d_in[0];
    const float* WQ = (const float*)d_in[1];
    const float* WK = (const float*)d_in[2];
    const float* WV = (const float*)d_in[3];
    float* out = (float*)d_out;

    __half *Xh, *T1h, *Vh, *Gh, *Wh, *P;
    float *RS, *INV;
    cudaGetSymbolAddress((void**)&Xh,  g_Xh);
    cudaGetSymbolAddress((void**)&T1h, g_T1h);
    cudaGetSymbolAddress((void**)&Vh,  g_Vh);
    cudaGetSymbolAddress((void**)&Gh,  g_Gh);
    cudaGetSymbolAddress((void**)&Wh,  g_Wh);
    cudaGetSymbolAddress((void**)&P,   g_P);
    cudaGetSymbolAddress((void**)&RS,  g_RS);
    cudaGetSymbolAddress((void**)&INV, g_INV);
    __half* Wqh = Wh;
    __half* Wkh = Wh + (size_t)D_ * U_;
    __half* Wvh = Wh + 2 * (size_t)D_ * U_;

    const int SMEM_NT = 3 * (9216 + 9216) * 2;    // 110592 B
    const int SMEM_NN = 3 * (9216 + 8704) * 2;    // 107520 B
    cudaFuncSetAttribute(gemm_f16<1, false>, cudaFuncAttributeMaxDynamicSharedMemorySize, SMEM_NT);
    cudaFuncSetAttribute(gemm_f16<1, true >, cudaFuncAttributeMaxDynamicSharedMemorySize, SMEM_NN);
    cudaFuncSetAttribute(gemm_f16<2, false>, cudaFuncAttributeMaxDynamicSharedMemorySize, SMEM_NT);
    cudaFuncSetAttribute(gemm_f16<3, true >, cudaFuncAttributeMaxDynamicSharedMemorySize, SMEM_NN);

    const int M = B_ * N_;                        // 16384
    const long long strXD = (long long)N_ * D_;   // per-batch row stride (X/T1/V)
    const long long strS  = (long long)N_ * N_;

    // 1) X -> half; Wq/Wk/Wv -> half (one batched launch, no transpose)
    to_half_kernel<<<(M * D_ / 4 + 255) / 256, 256>>>((const float4*)X, (__half2*)Xh, M * D_ / 4);
    dim3 g3((D_ * U_ / 4 + 255) / 256, 3);
    to_half3_kernel<<<g3, 256>>>((const float4*)WQ, (const float4*)WK,
                                 (const float4*)WV, (__half2*)Wh, D_ * U_ / 4);

    // 2) G = Wq @ Wk^T  [1024,1024]  (NT, tiny)
    dim3 gG(D_ / 128, D_ / 128, 1);
    gemm_f16<1, false><<<gG, 256, SMEM_NT>>>(Wqh, Wkh, Gh, U_, U_, U_, D_,
                                             0, 0, 0, 1.0f, nullptr);

    // 3) T1 = Xh @ G (NN);  V = Xh @ Wv (NN)   [16384,1024] each
    dim3 gT(D_ / 128, M / 128, 1);
    gemm_f16<1, true><<<gT, 256, SMEM_NN>>>(Xh, Gh, T1h, D_, D_, D_, D_,
                                            0, 0, 0, 1.0f, nullptr);
    gemm_f16<1, true><<<gT, 256, SMEM_NN>>>(Xh, Wvh, Vh, D_, D_, U_, U_,
                                            0, 0, 0, 1.0f, nullptr);

    // 4) scores + exp fused: P_b = exp((1/32) T1_b @ X_b^T), partials -> RS
    dim3 gS(N_ / 128, N_ / 128, B_);
    gemm_f16<2, false><<<gS, 256, SMEM_NT>>>(T1h, Xh, P, D_, D_, D_, N_,
                                             strXD, strXD, strS, 1.0f / 32.0f, RS);

    // 5) deterministic row-sum -> inverse
    rowinv_kernel<<<M / 256, 256>>>(RS, INV);

    // 6) out_b = (P_b @ V_b) * inv[row]   (NN)
    dim3 gO(U_ / 128, N_ / 128, B_);
    gemm_f16<3, true><<<gO, 256, SMEM_NN>>>(P, Vh, out, N_, N_, U_, U_,
                                            strS, strXD, strXD, 1.0f, INV);
}